// round 2
// baseline (speedup 1.0000x reference)
#include <cuda_runtime.h>

#define BB 32
#define NN 512
#define HH 8
#define DH 8
#define DO 32
#define FIN 16
#define ALPHAC 0.2f

// ---------- scratch (static device globals; no allocation) ----------
__device__ float g_Wh[BB*HH*NN*DH];        // 4 MB   [b][h][n][d]
__device__ float g_f1[BB*HH*NN];
__device__ float g_f2[BB*HH*NN];
__device__ unsigned short g_edges[(size_t)BB*NN*NN]; // 16.8 MB worst case
__device__ int   g_cnt[BB*NN];
__device__ float g_Who[BB*NN*DO];          // 2 MB
__device__ float g_g1[BB*NN];
__device__ float g_g2[BB*NN];
__device__ float g_out[BB*NN*DO];          // 2 MB  == A[32][16384]

// ---------- K1: Wh, f1, f2 ----------
__global__ void k1_prep(const float* __restrict__ xv,
                        const float* __restrict__ Wheads,
                        const float* __restrict__ a1,
                        const float* __restrict__ a2) {
    __shared__ float sW[HH*FIN*DH];     // 4 KB
    __shared__ float sa1[HH*DH], sa2[HH*DH];
    int tid = threadIdx.x;
    for (int t = tid; t < HH*FIN*DH; t += 128) sW[t] = Wheads[t];
    if (tid < HH*DH) { sa1[tid] = a1[tid]; sa2[tid] = a2[tid]; }
    __syncthreads();
    int gn = blockIdx.x * 128 + tid;          // b*N + n
    int b = gn >> 9, n = gn & (NN - 1);
    float x[FIN];
    const float4* xp = (const float4*)(xv + (size_t)gn * FIN);
    #pragma unroll
    for (int i = 0; i < 4; i++) {
        float4 v = xp[i];
        x[i*4+0] = v.x; x[i*4+1] = v.y; x[i*4+2] = v.z; x[i*4+3] = v.w;
    }
    #pragma unroll
    for (int h = 0; h < HH; h++) {
        float wh[DH];
        #pragma unroll
        for (int d = 0; d < DH; d++) {
            float s = 0.f;
            #pragma unroll
            for (int f = 0; f < FIN; f++)
                s += x[f] * sW[(h*FIN + f)*DH + d];
            wh[d] = s;
        }
        float f1v = 0.f, f2v = 0.f;
        #pragma unroll
        for (int d = 0; d < DH; d++) { f1v += wh[d]*sa1[h*DH+d]; f2v += wh[d]*sa2[h*DH+d]; }
        float* whp = g_Wh + ((size_t)(b*HH + h)*NN + n)*DH;
        ((float4*)whp)[0] = make_float4(wh[0], wh[1], wh[2], wh[3]);
        ((float4*)whp)[1] = make_float4(wh[4], wh[5], wh[6], wh[7]);
        g_f1[(b*HH + h)*NN + n] = f1v;
        g_f2[(b*HH + h)*NN + n] = f2v;
    }
}

// ---------- K2: edge compaction + GAT layer 1 + Who/g1/g2 ----------
__global__ void k2_gat(const float* __restrict__ adj,
                       const float* __restrict__ Wout,
                       const float* __restrict__ a1o,
                       const float* __restrict__ a2o) {
    int bi = blockIdx.x;               // b*N + i
    int b = bi >> 9;
    int i = bi & (NN - 1);
    int tid = threadIdx.x, lane = tid & 31, warp = tid >> 5;
    __shared__ unsigned short ej[NN];
    __shared__ float wbuf[NN];
    __shared__ float hc[HH*DH];
    __shared__ float sred[32];
    __shared__ float sbc;
    __shared__ int s_cnt;
    if (tid == 0) s_cnt = 0;
    __syncthreads();
    const float* arow = adj + (size_t)bi * NN;
    for (int t = tid; t < NN; t += 128)
        if (arow[t] > 0.f) { int p = atomicAdd(&s_cnt, 1); ej[p] = (unsigned short)t; }
    __syncthreads();
    int cnt = s_cnt;
    if (tid == 0) g_cnt[bi] = cnt;
    for (int t = tid; t < cnt; t += 128) g_edges[(size_t)bi*NN + t] = ej[t];
    bool uni = (cnt == 0);             // block-uniform branch
    int M = uni ? NN : cnt;

    for (int h = 0; h < HH; h++) {
        const float* f2p = g_f2 + (b*HH + h)*NN;
        float den;
        if (!uni) {
            float f1v = g_f1[(b*HH + h)*NN + i];
            float lm = -3.4e38f;
            for (int t = tid; t < cnt; t += 128) {
                float s = f1v + f2p[ej[t]];
                s = (s > 0.f) ? s : ALPHAC * s;
                wbuf[t] = s;
                lm = fmaxf(lm, s);
            }
            #pragma unroll
            for (int o = 16; o; o >>= 1) lm = fmaxf(lm, __shfl_xor_sync(0xffffffffu, lm, o));
            if (lane == 0) sred[warp] = lm;
            __syncthreads();
            if (tid == 0) sbc = fmaxf(fmaxf(sred[0], sred[1]), fmaxf(sred[2], sred[3]));
            __syncthreads();
            float m = sbc;
            float ls = 0.f;
            for (int t = tid; t < cnt; t += 128) {
                float w = __expf(wbuf[t] - m);
                wbuf[t] = w;
                ls += w;
            }
            #pragma unroll
            for (int o = 16; o; o >>= 1) ls += __shfl_xor_sync(0xffffffffu, ls, o);
            __syncthreads();
            if (lane == 0) sred[warp] = ls;
            __syncthreads();
            if (tid == 0) sbc = sred[0] + sred[1] + sred[2] + sred[3];
            __syncthreads();
            den = sbc;
        } else {
            den = (float)NN;
        }
        // accumulate h_d = sum_k w_k * Wh[j_k][d]; lane map: d = tid&7, k start tid>>3
        int d = tid & 7, ks = tid >> 3;
        float acc = 0.f;
        const float* whp = g_Wh + (size_t)(b*HH + h)*NN*DH;
        for (int k = ks; k < M; k += 16) {
            int j = uni ? k : ej[k];
            float w = uni ? 1.f : wbuf[k];
            acc += w * whp[j*DH + d];
        }
        acc += __shfl_down_sync(0xffffffffu, acc, 16);
        acc += __shfl_down_sync(0xffffffffu, acc, 8);
        if (lane < 8) sred[warp*8 + lane] = acc;
        __syncthreads();
        if (tid < 8) {
            float v = (sred[tid] + sred[8+tid] + sred[16+tid] + sred[24+tid]) / den;
            hc[h*DH + tid] = (v > 0.f) ? v : (__expf(v) - 1.f);   // ELU (concat heads)
        }
        __syncthreads();
    }
    // Who = h_cat @ W_out ; g1 = Who.a1o ; g2 = Who.a2o
    if (tid < DO) {
        float s = 0.f;
        #pragma unroll
        for (int f = 0; f < HH*DH; f++) s += hc[f] * Wout[f*DO + tid];
        g_Who[(size_t)bi*DO + tid] = s;
        float p1 = s * a1o[tid], p2 = s * a2o[tid];
        #pragma unroll
        for (int o = 16; o; o >>= 1) {
            p1 += __shfl_xor_sync(0xffffffffu, p1, o);
            p2 += __shfl_xor_sync(0xffffffffu, p2, o);
        }
        if (tid == 0) { g_g1[bi] = p1; g_g2[bi] = p2; }
    }
}

// ---------- K3: output attention layer ----------
__global__ void k3_out() {
    int bi = blockIdx.x;
    int b = bi >> 9;
    int tid = threadIdx.x, lane = tid & 31, warp = tid >> 5;
    __shared__ unsigned short ej[NN];
    __shared__ float wbuf[NN];
    __shared__ float sred[4*DO];
    __shared__ float sbc;
    int cnt = g_cnt[bi];
    for (int t = tid; t < cnt; t += 128) ej[t] = g_edges[(size_t)bi*NN + t];
    bool uni = (cnt == 0);
    int M = uni ? NN : cnt;
    float den;
    __syncthreads();
    if (!uni) {
        float g1v = g_g1[bi];
        const float* g2p = g_g2 + b*NN;
        float lm = -3.4e38f;
        for (int t = tid; t < cnt; t += 128) {
            float s = g1v + g2p[ej[t]];
            s = (s > 0.f) ? s : ALPHAC * s;
            wbuf[t] = s;
            lm = fmaxf(lm, s);
        }
        #pragma unroll
        for (int o = 16; o; o >>= 1) lm = fmaxf(lm, __shfl_xor_sync(0xffffffffu, lm, o));
        if (lane == 0) sred[warp] = lm;
        __syncthreads();
        if (tid == 0) sbc = fmaxf(fmaxf(sred[0], sred[1]), fmaxf(sred[2], sred[3]));
        __syncthreads();
        float m = sbc;
        float ls = 0.f;
        for (int t = tid; t < cnt; t += 128) {
            float w = __expf(wbuf[t] - m);
            wbuf[t] = w;
            ls += w;
        }
        #pragma unroll
        for (int o = 16; o; o >>= 1) ls += __shfl_xor_sync(0xffffffffu, ls, o);
        __syncthreads();
        if (lane == 0) sred[warp] = ls;
        __syncthreads();
        if (tid == 0) sbc = sred[0] + sred[1] + sred[2] + sred[3];
        __syncthreads();
        den = sbc;
    } else {
        den = (float)NN;
    }
    // accumulate out_d = sum_k w_k * Who[j_k][d]; warp strides k, lane = d
    float acc = 0.f;
    for (int k = warp; k < M; k += 4) {
        int j = uni ? k : ej[k];
        float w = uni ? 1.f : wbuf[k];
        acc += w * g_Who[((size_t)b*NN + j)*DO + lane];
    }
    sred[warp*DO + lane] = acc;
    __syncthreads();
    if (tid < DO) {
        float v = (sred[tid] + sred[DO+tid] + sred[2*DO+tid] + sred[3*DO+tid]) / den;
        g_out[(size_t)bi*DO + tid] = (v > 0.f) ? v : (__expf(v) - 1.f);   // final F.elu
    }
}

// ---------- K init: q = b_q ----------
__global__ void k_initq(const float* __restrict__ bq, float* __restrict__ q) {
    int idx = blockIdx.x * 256 + threadIdx.x;
    if (idx < BB*NN) q[idx] = bq[idx & (NN - 1)];
}

// ---------- K4: q += out.reshape(B, N*DO) @ W_q  (split-K fp32 GEMM) ----------
// grid: 8 n-tiles (64 cols) x 64 k-splits (256 rows) = 512 blocks, 256 threads
__global__ void k4_gemm(const float* __restrict__ Wq, float* __restrict__ q) {
    __shared__ float a_s[64][36];       // [kk][b], padded
    int tid = threadIdx.x;
    int nt = blockIdx.x & 7;
    int ksp = blockIdx.x >> 3;
    int n0 = nt * 64, k0 = ksp * 256;
    int nl = tid & 63, bg = tid >> 6;   // 4 groups of 8 b
    float acc[8];
    #pragma unroll
    for (int r = 0; r < 8; r++) acc[r] = 0.f;
    for (int kt = 0; kt < 256; kt += 64) {
        __syncthreads();
        for (int idx = tid; idx < 2048; idx += 256) {
            int bb = idx >> 6, kk = idx & 63;
            a_s[kk][bb] = g_out[(size_t)bb*(NN*DO) + k0 + kt + kk];
        }
        __syncthreads();
        const float* wp = Wq + (size_t)(k0 + kt)*NN + n0 + nl;
        #pragma unroll 16
        for (int kk = 0; kk < 64; kk++) {
            float w = wp[(size_t)kk * NN];
            float4 av0 = *(const float4*)&a_s[kk][bg*8];
            float4 av1 = *(const float4*)&a_s[kk][bg*8 + 4];
            acc[0] += av0.x * w; acc[1] += av0.y * w; acc[2] += av0.z * w; acc[3] += av0.w * w;
            acc[4] += av1.x * w; acc[5] += av1.y * w; acc[6] += av1.z * w; acc[7] += av1.w * w;
        }
    }
    #pragma unroll
    for (int r = 0; r < 8; r++)
        atomicAdd(&q[(bg*8 + r)*NN + n0 + nl], acc[r]);
}

extern "C" void kernel_launch(void* const* d_in, const int* in_sizes, int n_in,
                              void* d_out, int out_size) {
    const float* xv     = (const float*)d_in[0];
    const float* adj    = (const float*)d_in[1];
    const float* Wheads = (const float*)d_in[2];
    const float* a1     = (const float*)d_in[3];
    const float* a2     = (const float*)d_in[4];
    const float* Wout   = (const float*)d_in[5];
    const float* a1o    = (const float*)d_in[6];
    const float* a2o    = (const float*)d_in[7];
    const float* Wq     = (const float*)d_in[8];
    const float* bq     = (const float*)d_in[9];
    float* q = (float*)d_out;

    k1_prep<<<128, 128>>>(xv, Wheads, a1, a2);
    k2_gat<<<BB*NN, 128>>>(adj, Wout, a1o, a2o);
    k3_out<<<BB*NN, 128>>>();
    k_initq<<<64, 256>>>(bq, q);
    k4_gemm<<<512, 256>>>(Wq, q);
}

// round 3
// speedup vs baseline: 1.8317x; 1.8317x over previous
#include <cuda_runtime.h>

#define BB 32
#define NN 512
#define HH 8
#define DH 8
#define DO 32
#define FIN 16
#define ALPHAC 0.2f
#define FULLM 0xffffffffu

// ---------- scratch (static device globals; no allocation) ----------
__device__ float g_Wh[BB*HH*NN*DH];        // 4 MB   [b][h][n][d]
__device__ float g_f1[BB*HH*NN];
__device__ float g_f2[BB*HH*NN];
__device__ unsigned short g_edges[(size_t)BB*NN*NN]; // worst case
__device__ int   g_cnt[BB*NN];
__device__ float g_Who[BB*NN*DO];          // 2 MB
__device__ float g_g1[BB*NN];
__device__ float g_g2[BB*NN];
__device__ float g_out[BB*NN*DO];          // 2 MB  == A[32][16384]

// ---------- K1: Wh, f1, f2 ----------
__global__ void k1_prep(const float* __restrict__ xv,
                        const float* __restrict__ Wheads,
                        const float* __restrict__ a1,
                        const float* __restrict__ a2) {
    __shared__ float sW[HH*FIN*DH];     // 4 KB
    __shared__ float sa1[HH*DH], sa2[HH*DH];
    int tid = threadIdx.x;
    for (int t = tid; t < HH*FIN*DH; t += 128) sW[t] = Wheads[t];
    if (tid < HH*DH) { sa1[tid] = a1[tid]; sa2[tid] = a2[tid]; }
    __syncthreads();
    int gn = blockIdx.x * 128 + tid;          // b*N + n
    int b = gn >> 9, n = gn & (NN - 1);
    float x[FIN];
    const float4* xp = (const float4*)(xv + (size_t)gn * FIN);
    #pragma unroll
    for (int i = 0; i < 4; i++) {
        float4 v = xp[i];
        x[i*4+0] = v.x; x[i*4+1] = v.y; x[i*4+2] = v.z; x[i*4+3] = v.w;
    }
    #pragma unroll
    for (int h = 0; h < HH; h++) {
        float wh[DH];
        #pragma unroll
        for (int d = 0; d < DH; d++) {
            float s = 0.f;
            #pragma unroll
            for (int f = 0; f < FIN; f++)
                s += x[f] * sW[(h*FIN + f)*DH + d];
            wh[d] = s;
        }
        float f1v = 0.f, f2v = 0.f;
        #pragma unroll
        for (int d = 0; d < DH; d++) { f1v += wh[d]*sa1[h*DH+d]; f2v += wh[d]*sa2[h*DH+d]; }
        float* whp = g_Wh + ((size_t)(b*HH + h)*NN + n)*DH;
        ((float4*)whp)[0] = make_float4(wh[0], wh[1], wh[2], wh[3]);
        ((float4*)whp)[1] = make_float4(wh[4], wh[5], wh[6], wh[7]);
        g_f1[(b*HH + h)*NN + n] = f1v;
        g_f2[(b*HH + h)*NN + n] = f2v;
    }
}

// ---------- K2: warp-per-row: edge compaction + GAT layer1 + Who/g1/g2 ----------
// grid = BB*NN/8 blocks, 256 threads (8 warps); warp w handles row blockIdx.x*8+w
__global__ void k2_gat(const float* __restrict__ adj,
                       const float* __restrict__ Wout,
                       const float* __restrict__ a1o,
                       const float* __restrict__ a2o) {
    __shared__ unsigned short ej[8][NN];
    __shared__ float wbuf[8][NN];
    __shared__ float hcw[8][HH*DH];
    int wid = threadIdx.x >> 5, lane = threadIdx.x & 31;
    int bi = blockIdx.x * 8 + wid;           // b*N + i
    int b = bi >> 9, i = bi & (NN - 1);

    // ordered, deterministic edge compaction via ballot
    const float* arow = adj + (size_t)bi * NN;
    int cnt = 0;
    #pragma unroll 4
    for (int t0 = 0; t0 < NN; t0 += 32) {
        float v = arow[t0 + lane];
        unsigned m = __ballot_sync(FULLM, v > 0.f);
        if (v > 0.f) ej[wid][cnt + __popc(m & ((1u << lane) - 1u))] = (unsigned short)(t0 + lane);
        cnt += __popc(m);
    }
    if (lane == 0) g_cnt[bi] = cnt;
    __syncwarp();
    for (int t = lane; t < cnt; t += 32) g_edges[(size_t)bi*NN + t] = ej[wid][t];
    bool uni = (cnt == 0);
    int M = uni ? NN : cnt;

    #pragma unroll 1
    for (int h = 0; h < HH; h++) {
        const float* f2p = g_f2 + (b*HH + h)*NN;
        float den;
        if (!uni) {
            float f1v = g_f1[(b*HH + h)*NN + i];
            float lm = -3.4e38f;
            for (int t = lane; t < cnt; t += 32) {
                float s = f1v + f2p[ej[wid][t]];
                s = (s > 0.f) ? s : ALPHAC * s;
                wbuf[wid][t] = s;
                lm = fmaxf(lm, s);
            }
            #pragma unroll
            for (int o = 16; o; o >>= 1) lm = fmaxf(lm, __shfl_xor_sync(FULLM, lm, o));
            float ls = 0.f;
            for (int t = lane; t < cnt; t += 32) {
                float w = __expf(wbuf[wid][t] - lm);
                wbuf[wid][t] = w;
                ls += w;
            }
            #pragma unroll
            for (int o = 16; o; o >>= 1) ls += __shfl_xor_sync(FULLM, ls, o);
            den = ls;
            __syncwarp();
        } else {
            den = (float)NN;
        }
        // aggregate: lane = (kslot<<3)|d ; 4 kslots x 8 dims
        int d = lane & 7, ks = lane >> 3;
        float acc = 0.f;
        const float* whp = g_Wh + (size_t)(b*HH + h)*NN*DH;
        for (int k = ks; k < M; k += 4) {
            int j = uni ? k : ej[wid][k];
            float w = uni ? 1.f : wbuf[wid][k];
            acc += w * whp[j*DH + d];
        }
        acc += __shfl_down_sync(FULLM, acc, 16);
        acc += __shfl_down_sync(FULLM, acc, 8);
        if (lane < 8) {
            float v = acc / den;
            hcw[wid][h*DH + lane] = (v > 0.f) ? v : (__expf(v) - 1.f);   // ELU (heads)
        }
        __syncwarp();
    }
    // Who = h_cat @ W_out (lane = output dim); g1,g2 reductions
    float s = 0.f;
    #pragma unroll
    for (int f = 0; f < HH*DH; f++) s += hcw[wid][f] * Wout[f*DO + lane];
    g_Who[(size_t)bi*DO + lane] = s;
    float p1 = s * a1o[lane], p2 = s * a2o[lane];
    #pragma unroll
    for (int o = 16; o; o >>= 1) {
        p1 += __shfl_xor_sync(FULLM, p1, o);
        p2 += __shfl_xor_sync(FULLM, p2, o);
    }
    if (lane == 0) { g_g1[bi] = p1; g_g2[bi] = p2; }
}

// ---------- K3: warp-per-row output attention (lane = output dim) ----------
__global__ void k3_out() {
    __shared__ unsigned short ej[8][NN];
    __shared__ float wbuf[8][NN];
    int wid = threadIdx.x >> 5, lane = threadIdx.x & 31;
    int bi = blockIdx.x * 8 + wid;
    int b = bi >> 9;
    int cnt = g_cnt[bi];
    for (int t = lane; t < cnt; t += 32) ej[wid][t] = g_edges[(size_t)bi*NN + t];
    bool uni = (cnt == 0);
    int M = uni ? NN : cnt;
    float den;
    __syncwarp();
    if (!uni) {
        float g1v = g_g1[bi];
        const float* g2p = g_g2 + b*NN;
        float lm = -3.4e38f;
        for (int t = lane; t < cnt; t += 32) {
            float s = g1v + g2p[ej[wid][t]];
            s = (s > 0.f) ? s : ALPHAC * s;
            wbuf[wid][t] = s;
            lm = fmaxf(lm, s);
        }
        #pragma unroll
        for (int o = 16; o; o >>= 1) lm = fmaxf(lm, __shfl_xor_sync(FULLM, lm, o));
        float ls = 0.f;
        for (int t = lane; t < cnt; t += 32) {
            float w = __expf(wbuf[wid][t] - lm);
            wbuf[wid][t] = w;
            ls += w;
        }
        #pragma unroll
        for (int o = 16; o; o >>= 1) ls += __shfl_xor_sync(FULLM, ls, o);
        den = ls;
        __syncwarp();
    } else {
        den = (float)NN;
    }
    float acc = 0.f;
    const float* whop = g_Who + (size_t)b*NN*DO;
    for (int k = 0; k < M; k++) {
        int j = uni ? k : ej[wid][k];
        float w = uni ? 1.f : wbuf[wid][k];
        acc += w * whop[j*DO + lane];          // coalesced 128B per edge
    }
    float v = acc / den;
    g_out[(size_t)bi*DO + lane] = (v > 0.f) ? v : (__expf(v) - 1.f);   // final elu
}

// ---------- K init: q = b_q ----------
__global__ void k_initq(const float* __restrict__ bq, float* __restrict__ q) {
    int idx = blockIdx.x * 256 + threadIdx.x;
    if (idx < BB*NN) q[idx] = bq[idx & (NN - 1)];
}

// ---------- K4: q += out.reshape(B, N*DO) @ W_q  (split-K fp32 GEMM) ----------
// grid: 8 n-tiles (64 cols) x 64 k-splits (256 rows) = 512 blocks, 256 threads
__global__ void k4_gemm(const float* __restrict__ Wq, float* __restrict__ q) {
    __shared__ float a_s[64][36];       // [kk][b], padded
    int tid = threadIdx.x;
    int nt = blockIdx.x & 7;
    int ksp = blockIdx.x >> 3;
    int n0 = nt * 64, k0 = ksp * 256;
    int nl = tid & 63, bg = tid >> 6;   // 4 groups of 8 b
    float acc[8];
    #pragma unroll
    for (int r = 0; r < 8; r++) acc[r] = 0.f;
    for (int kt = 0; kt < 256; kt += 64) {
        __syncthreads();
        for (int idx = tid; idx < 2048; idx += 256) {
            int bb = idx >> 6, kk = idx & 63;
            a_s[kk][bb] = g_out[(size_t)bb*(NN*DO) + k0 + kt + kk];
        }
        __syncthreads();
        const float* wp = Wq + (size_t)(k0 + kt)*NN + n0 + nl;
        #pragma unroll 16
        for (int kk = 0; kk < 64; kk++) {
            float w = wp[(size_t)kk * NN];
            float4 av0 = *(const float4*)&a_s[kk][bg*8];
            float4 av1 = *(const float4*)&a_s[kk][bg*8 + 4];
            acc[0] += av0.x * w; acc[1] += av0.y * w; acc[2] += av0.z * w; acc[3] += av0.w * w;
            acc[4] += av1.x * w; acc[5] += av1.y * w; acc[6] += av1.z * w; acc[7] += av1.w * w;
        }
    }
    #pragma unroll
    for (int r = 0; r < 8; r++)
        atomicAdd(&q[(bg*8 + r)*NN + n0 + nl], acc[r]);
}

extern "C" void kernel_launch(void* const* d_in, const int* in_sizes, int n_in,
                              void* d_out, int out_size) {
    const float* xv     = (const float*)d_in[0];
    const float* adj    = (const float*)d_in[1];
    const float* Wheads = (const float*)d_in[2];
    const float* a1     = (const float*)d_in[3];
    const float* a2     = (const float*)d_in[4];
    const float* Wout   = (const float*)d_in[5];
    const float* a1o    = (const float*)d_in[6];
    const float* a2o    = (const float*)d_in[7];
    const float* Wq     = (const float*)d_in[8];
    const float* bq     = (const float*)d_in[9];
    float* q = (float*)d_out;

    k1_prep<<<128, 128>>>(xv, Wheads, a1, a2);
    k2_gat<<<BB*NN/8, 256>>>(adj, Wout, a1o, a2o);
    k3_out<<<BB*NN/8, 256>>>();
    k_initq<<<64, 256>>>(bq, q);
    k4_gemm<<<512, 256>>>(Wq, q);
}

// round 4
// speedup vs baseline: 2.2723x; 1.2405x over previous
#include <cuda_runtime.h>

#define BB 32
#define NN 512
#define HH 8
#define DH 8
#define DO 32
#define FIN 16
#define ALPHAC 0.2f
#define FULLM 0xffffffffu
#define EMAX 128          // fast-path edge cap (P(cnt>128) ~ 0; fallback is correct)

// ---------- scratch (static device globals; no allocation) ----------
__device__ float g_Wh2[BB*NN*64];          // 8 MB  [b][n][h*8+d]
__device__ float g_f1v[BB*NN*HH];          // [b][n][h]
__device__ float g_f2v[BB*NN*HH];          // [b][n][h]
__device__ unsigned short g_edges[(size_t)BB*NN*NN];
__device__ int   g_cnt[BB*NN];
__device__ float g_Who[BB*NN*DO];          // 2 MB
__device__ float g_g1[BB*NN];
__device__ float g_g2[BB*NN];
__device__ float g_out[BB*NN*DO];          // 2 MB == A[32][16384]
__device__ float g_part[64 * BB * NN];     // 4 MB  split-K partials

// ---------- K1: Wh (node-major), f1, f2 ----------
__global__ void k1_prep(const float* __restrict__ xv,
                        const float* __restrict__ Wheads,
                        const float* __restrict__ a1,
                        const float* __restrict__ a2) {
    __shared__ float sW[HH*FIN*DH];
    __shared__ float sa1[HH*DH], sa2[HH*DH];
    int tid = threadIdx.x;
    for (int t = tid; t < HH*FIN*DH; t += 128) sW[t] = Wheads[t];
    if (tid < HH*DH) { sa1[tid] = a1[tid]; sa2[tid] = a2[tid]; }
    __syncthreads();
    int gn = blockIdx.x * 128 + tid;          // b*N + n
    float x[FIN];
    const float4* xp = (const float4*)(xv + (size_t)gn * FIN);
    #pragma unroll
    for (int i = 0; i < 4; i++) {
        float4 v = xp[i];
        x[i*4+0] = v.x; x[i*4+1] = v.y; x[i*4+2] = v.z; x[i*4+3] = v.w;
    }
    float* whp = g_Wh2 + (size_t)gn * 64;
    #pragma unroll
    for (int h = 0; h < HH; h++) {
        float wh[DH];
        #pragma unroll
        for (int d = 0; d < DH; d++) {
            float s = 0.f;
            #pragma unroll
            for (int f = 0; f < FIN; f++)
                s += x[f] * sW[(h*FIN + f)*DH + d];
            wh[d] = s;
        }
        float f1v = 0.f, f2v = 0.f;
        #pragma unroll
        for (int d = 0; d < DH; d++) { f1v += wh[d]*sa1[h*DH+d]; f2v += wh[d]*sa2[h*DH+d]; }
        ((float4*)(whp + h*8))[0] = make_float4(wh[0], wh[1], wh[2], wh[3]);
        ((float4*)(whp + h*8))[1] = make_float4(wh[4], wh[5], wh[6], wh[7]);
        g_f1v[(size_t)gn*HH + h] = f1v;
        g_f2v[(size_t)gn*HH + h] = f2v;
    }
}

// ---------- K2: warp-per-row, single-pass 8-head attention ----------
// grid = BB*NN/8 blocks, 256 threads; warp w handles row blockIdx.x*8+w
__global__ void k2_gat(const float* __restrict__ adj,
                       const float* __restrict__ Wout,
                       const float* __restrict__ a1o,
                       const float* __restrict__ a2o) {
    __shared__ unsigned short ej[8][NN];       // 8 KB
    __shared__ float wsm[8][EMAX*HH];          // 32 KB (also flat scratch in fallback)
    __shared__ float hcsm[8][64];              // 2 KB
    int wid = threadIdx.x >> 5, lane = threadIdx.x & 31;
    int bi = blockIdx.x * 8 + wid;             // b*N + i
    int b = bi >> 9, i = bi & (NN - 1);

    // deterministic ordered edge compaction (ballot)
    const float* arow = adj + (size_t)bi * NN;
    int cnt = 0;
    #pragma unroll 4
    for (int t0 = 0; t0 < NN; t0 += 32) {
        float v = arow[t0 + lane];
        unsigned m = __ballot_sync(FULLM, v > 0.f);
        if (v > 0.f) ej[wid][cnt + __popc(m & ((1u << lane) - 1u))] = (unsigned short)(t0 + lane);
        cnt += __popc(m);
    }
    if (lane == 0) g_cnt[bi] = cnt;
    __syncwarp();
    for (int t = lane; t < cnt; t += 32) g_edges[(size_t)bi*NN + t] = ej[wid][t];

    const float* f2p = g_f2v + (size_t)b*NN*HH;
    const float* whb = g_Wh2 + (size_t)b*NN*64;

    if (cnt > 0 && cnt <= EMAX) {
        // ---- fast path: all 8 heads at once, lane-per-edge ----
        float4 f1a = *(const float4*)(g_f1v + (size_t)bi*HH);
        float4 f1b = *(const float4*)(g_f1v + (size_t)bi*HH + 4);
        float f1r[8] = {f1a.x, f1a.y, f1a.z, f1a.w, f1b.x, f1b.y, f1b.z, f1b.w};
        int ns = (cnt + 31) >> 5;
        float sc[4][8];
        #pragma unroll
        for (int s = 0; s < 4; s++) {
            if (s < ns) {                       // warp-uniform branch
                int k = s*32 + lane;
                bool act = k < cnt;
                int j = act ? ej[wid][k] : ej[wid][0];
                float4 u = *(const float4*)(f2p + j*8);
                float4 v = *(const float4*)(f2p + j*8 + 4);
                float t8[8] = {u.x,u.y,u.z,u.w,v.x,v.y,v.z,v.w};
                #pragma unroll
                for (int h = 0; h < 8; h++) {
                    float s2 = f1r[h] + t8[h];
                    s2 = (s2 > 0.f) ? s2 : ALPHAC * s2;
                    sc[s][h] = act ? s2 : -3.4e38f;
                }
            } else {
                #pragma unroll
                for (int h = 0; h < 8; h++) sc[s][h] = -3.4e38f;
            }
        }
        // max over slots+lanes (all heads concurrently)
        float mx[8];
        #pragma unroll
        for (int h = 0; h < 8; h++) mx[h] = sc[0][h];
        #pragma unroll
        for (int s = 1; s < 4; s++) {
            #pragma unroll
            for (int h = 0; h < 8; h++) mx[h] = fmaxf(mx[h], sc[s][h]);
        }
        #pragma unroll
        for (int o = 16; o; o >>= 1) {
            #pragma unroll
            for (int h = 0; h < 8; h++) mx[h] = fmaxf(mx[h], __shfl_xor_sync(FULLM, mx[h], o));
        }
        // exp + sum
        float sm[8] = {0,0,0,0,0,0,0,0};
        #pragma unroll
        for (int s = 0; s < 4; s++) {
            if (s < ns) {
                #pragma unroll
                for (int h = 0; h < 8; h++) {
                    float w = __expf(sc[s][h] - mx[h]);
                    sc[s][h] = w;
                    sm[h] += w;
                }
            }
        }
        #pragma unroll
        for (int o = 16; o; o >>= 1) {
            #pragma unroll
            for (int h = 0; h < 8; h++) sm[h] += __shfl_xor_sync(FULLM, sm[h], o);
        }
        float inv[8];
        #pragma unroll
        for (int h = 0; h < 8; h++) inv[h] = 1.0f / sm[h];
        // store normalized weights [k][h]
        #pragma unroll
        for (int s = 0; s < 4; s++) {
            if (s < ns) {
                int k = s*32 + lane;
                if (k < cnt) {
                    #pragma unroll
                    for (int h = 0; h < 8; h++) wsm[wid][k*8 + h] = sc[s][h] * inv[h];
                }
            }
        }
        __syncwarp();
        // aggregate: lane covers dims {2*lane, 2*lane+1}; h = lane>>2
        int h = lane >> 2;
        float acc0 = 0.f, acc1 = 0.f;
        #pragma unroll 4
        for (int k = 0; k < cnt; k++) {
            int j = ej[wid][k];
            float w = wsm[wid][k*8 + h];
            float2 wv = *(const float2*)(whb + (size_t)j*64 + 2*lane);
            acc0 += w * wv.x; acc1 += w * wv.y;
        }
        acc0 = (acc0 > 0.f) ? acc0 : (__expf(acc0) - 1.f);
        acc1 = (acc1 > 0.f) ? acc1 : (__expf(acc1) - 1.f);
        hcsm[wid][2*lane]   = acc0;
        hcsm[wid][2*lane+1] = acc1;
    } else if (cnt == 0) {
        // uniform attention: mean over all 512 nodes
        float acc0 = 0.f, acc1 = 0.f;
        #pragma unroll 4
        for (int j = 0; j < NN; j++) {
            float2 wv = *(const float2*)(whb + (size_t)j*64 + 2*lane);
            acc0 += wv.x; acc1 += wv.y;
        }
        acc0 *= (1.0f/NN); acc1 *= (1.0f/NN);
        acc0 = (acc0 > 0.f) ? acc0 : (__expf(acc0) - 1.f);
        acc1 = (acc1 > 0.f) ? acc1 : (__expf(acc1) - 1.f);
        hcsm[wid][2*lane]   = acc0;
        hcsm[wid][2*lane+1] = acc1;
    } else {
        // fallback: per-head, scratch = wsm flat (>=512 floats)
        float* wf = &wsm[wid][0];
        for (int h = 0; h < HH; h++) {
            float f1v = g_f1v[(size_t)bi*HH + h];
            float lm = -3.4e38f;
            for (int t = lane; t < cnt; t += 32) {
                float s = f1v + f2p[(size_t)ej[wid][t]*HH + h];
                s = (s > 0.f) ? s : ALPHAC * s;
                wf[t] = s;
                lm = fmaxf(lm, s);
            }
            #pragma unroll
            for (int o = 16; o; o >>= 1) lm = fmaxf(lm, __shfl_xor_sync(FULLM, lm, o));
            float ls = 0.f;
            for (int t = lane; t < cnt; t += 32) {
                float w = __expf(wf[t] - lm);
                wf[t] = w;
                ls += w;
            }
            #pragma unroll
            for (int o = 16; o; o >>= 1) ls += __shfl_xor_sync(FULLM, ls, o);
            __syncwarp();
            int d = lane & 7, ks = lane >> 3;
            float acc = 0.f;
            for (int k = ks; k < cnt; k += 4)
                acc += wf[k] * whb[(size_t)ej[wid][k]*64 + h*8 + d];
            acc += __shfl_down_sync(FULLM, acc, 16);
            acc += __shfl_down_sync(FULLM, acc, 8);
            if (lane < 8) {
                float v = acc / ls;
                hcsm[wid][h*8 + lane] = (v > 0.f) ? v : (__expf(v) - 1.f);
            }
            __syncwarp();
        }
    }
    __syncwarp();
    // Who = h_cat @ W_out (lane = out dim); g1,g2
    float s = 0.f;
    #pragma unroll
    for (int f = 0; f < HH*DH; f++) s += hcsm[wid][f] * Wout[f*DO + lane];
    g_Who[(size_t)bi*DO + lane] = s;
    float p1 = s * a1o[lane], p2 = s * a2o[lane];
    #pragma unroll
    for (int o = 16; o; o >>= 1) {
        p1 += __shfl_xor_sync(FULLM, p1, o);
        p2 += __shfl_xor_sync(FULLM, p2, o);
    }
    if (lane == 0) { g_g1[bi] = p1; g_g2[bi] = p2; }
}

// ---------- K3: warp-per-row output attention (lane = output dim) ----------
__global__ void k3_out() {
    __shared__ unsigned short ej[8][NN];
    __shared__ float wbuf[8][NN];
    int wid = threadIdx.x >> 5, lane = threadIdx.x & 31;
    int bi = blockIdx.x * 8 + wid;
    int b = bi >> 9;
    int cnt = g_cnt[bi];
    for (int t = lane; t < cnt; t += 32) ej[wid][t] = g_edges[(size_t)bi*NN + t];
    bool uni = (cnt == 0);
    int M = uni ? NN : cnt;
    float den;
    __syncwarp();
    if (!uni) {
        float g1v = g_g1[bi];
        const float* g2p = g_g2 + b*NN;
        float lm = -3.4e38f;
        for (int t = lane; t < cnt; t += 32) {
            float s = g1v + g2p[ej[wid][t]];
            s = (s > 0.f) ? s : ALPHAC * s;
            wbuf[wid][t] = s;
            lm = fmaxf(lm, s);
        }
        #pragma unroll
        for (int o = 16; o; o >>= 1) lm = fmaxf(lm, __shfl_xor_sync(FULLM, lm, o));
        float ls = 0.f;
        for (int t = lane; t < cnt; t += 32) {
            float w = __expf(wbuf[wid][t] - lm);
            wbuf[wid][t] = w;
            ls += w;
        }
        #pragma unroll
        for (int o = 16; o; o >>= 1) ls += __shfl_xor_sync(FULLM, ls, o);
        den = ls;
        __syncwarp();
    } else {
        den = (float)NN;
    }
    float acc = 0.f;
    const float* whop = g_Who + (size_t)b*NN*DO;
    #pragma unroll 4
    for (int k = 0; k < M; k++) {
        int j = uni ? k : ej[wid][k];
        float w = uni ? 1.f : wbuf[wid][k];
        acc += w * whop[j*DO + lane];          // coalesced 128B per edge
    }
    float v = acc / den;
    g_out[(size_t)bi*DO + lane] = (v > 0.f) ? v : (__expf(v) - 1.f);   // final elu
}

// ---------- K4: split-K GEMM -> deterministic partials ----------
// grid: 8 n-tiles (64 cols) x 64 k-splits (256 rows) = 512 blocks, 256 threads
__global__ void k4_gemm(const float* __restrict__ Wq) {
    __shared__ float a_s[64][36];
    int tid = threadIdx.x;
    int nt = blockIdx.x & 7;
    int ksp = blockIdx.x >> 3;
    int n0 = nt * 64, k0 = ksp * 256;
    int nl = tid & 63, bg = tid >> 6;
    float acc[8];
    #pragma unroll
    for (int r = 0; r < 8; r++) acc[r] = 0.f;
    for (int kt = 0; kt < 256; kt += 64) {
        __syncthreads();
        for (int idx = tid; idx < 2048; idx += 256) {
            int bb = idx >> 6, kk = idx & 63;
            a_s[kk][bb] = g_out[(size_t)bb*(NN*DO) + k0 + kt + kk];
        }
        __syncthreads();
        const float* wp = Wq + (size_t)(k0 + kt)*NN + n0 + nl;
        #pragma unroll 16
        for (int kk = 0; kk < 64; kk++) {
            float w = wp[(size_t)kk * NN];
            float4 av0 = *(const float4*)&a_s[kk][bg*8];
            float4 av1 = *(const float4*)&a_s[kk][bg*8 + 4];
            acc[0] += av0.x * w; acc[1] += av0.y * w; acc[2] += av0.z * w; acc[3] += av0.w * w;
            acc[4] += av1.x * w; acc[5] += av1.y * w; acc[6] += av1.z * w; acc[7] += av1.w * w;
        }
    }
    float* dst = g_part + (size_t)ksp * (BB*NN);
    #pragma unroll
    for (int r = 0; r < 8; r++)
        dst[(bg*8 + r)*NN + n0 + nl] = acc[r];
}

// ---------- K5: deterministic reduce + bias ----------
__global__ void k5_reduce(const float* __restrict__ bq, float* __restrict__ q) {
    int idx = blockIdx.x * 256 + threadIdx.x;   // 64 blocks x 256 = 16384
    float s = bq[idx & (NN - 1)];
    #pragma unroll 16
    for (int p = 0; p < 64; p++)
        s += g_part[(size_t)p * (BB*NN) + idx];
    q[idx] = s;
}

extern "C" void kernel_launch(void* const* d_in, const int* in_sizes, int n_in,
                              void* d_out, int out_size) {
    const float* xv     = (const float*)d_in[0];
    const float* adj    = (const float*)d_in[1];
    const float* Wheads = (const float*)d_in[2];
    const float* a1     = (const float*)d_in[3];
    const float* a2     = (const float*)d_in[4];
    const float* Wout   = (const float*)d_in[5];
    const float* a1o    = (const float*)d_in[6];
    const float* a2o    = (const float*)d_in[7];
    const float* Wq     = (const float*)d_in[8];
    const float* bq     = (const float*)d_in[9];
    float* q = (float*)d_out;

    k1_prep<<<128, 128>>>(xv, Wheads, a1, a2);
    k2_gat<<<BB*NN/8, 256>>>(adj, Wout, a1o, a2o);
    k3_out<<<BB*NN/8, 256>>>();
    k4_gemm<<<512, 256>>>(Wq);
    k5_reduce<<<64, 256>>>(bq, q);
}